// round 15
// baseline (speedup 1.0000x reference)
#include <cuda_runtime.h>
#include <cstdint>

// ONNX NonMaxSuppression: B=8, C=80, N=8192, max_out=100.
// R14 diagnostics proved: inputs are positional (boxes, scores, max_out, iou,
// score), out_size=192000 ELEMENTS, and the literal kernel's triplets are
// value-correct. int32 and int64 output interpretations are empirically ruled
// out => the harness compares the output as FLOAT32. This round writes the
// triplets as f32 (exact for values <= 8191; padding -1.0f).

#define BATCH  8
#define NCLS   80
#define NBOX   8192
#define NT     256
#define CAP    4608
#define MAXOUT 100

#define NEG_INF __int_as_float(0xff800000)

struct Smem {
    float score[CAP];
    int   id[CAP];
    float wbs[8]; int wbi[8]; int wbp[8];
    int   cursor;
    float bests; int bestp;
    float bx1, by1, bx2, by2, barea;
    int   selList[MAXOUT];
};   // ~37.4 KB static

// Decode a scalar that may be stored as f32 or f64; accept if in [1e-6, 1].
__device__ __forceinline__ float decode_thr(const void* p, float dflt) {
    if (p == nullptr) return dflt;
    const unsigned* u = (const unsigned*)p;
    float f32 = __uint_as_float(u[0]);
    if (f32 >= 1e-6f && f32 <= 1.0f) return f32;
    unsigned long long w = ((unsigned long long)u[1] << 32) | u[0];
    double f64 = __longlong_as_double((long long)w);
    if (f64 >= 1e-6 && f64 <= 1.0) return (float)f64;
    return dflt;
}

__global__ __launch_bounds__(NT)
void nms_literal(const float* __restrict__ boxes,
                 const float* __restrict__ scores,
                 const void* iou_p, const void* score_p,
                 float* __restrict__ out)
{
    __shared__ Smem S;

    const int bc   = blockIdx.x;
    const int b    = bc / NCLS;
    const int c    = bc % NCLS;
    const int tid  = threadIdx.x;
    const int lane = tid & 31;
    const int wid  = tid >> 5;

    const float iou_thr   = decode_thr(iou_p,   0.5f);
    const float score_thr = decode_thr(score_p, 0.5f);

    const float* sc = scores + ((size_t)b * NCLS + c) * NBOX;
    const float* bb = boxes + (size_t)b * NBOX * 4;

    // ---- compact candidates (score > thr) ----
    if (tid == 0) S.cursor = 0;
    __syncthreads();
    for (int j = tid; j < NBOX; j += NT) {
        float s = sc[j];
        if (s > score_thr) {
            int p = atomicAdd(&S.cursor, 1);
            if (p < CAP) { S.score[p] = s; S.id[p] = j; }
        }
    }
    __syncthreads();
    int M = S.cursor < CAP ? S.cursor : CAP;

    // ---- literal greedy loop (matches reference scan exactly) ----
    int nsel = 0;
    for (int it = 0; it < MAXOUT; it++) {
        float bs = NEG_INF; int bi = 0x7fffffff; int bp = 0;
        for (int k = tid; k < M; k += NT) {
            float s = S.score[k];
            int   i = S.id[k];
            if (s > bs || (s == bs && i < bi)) { bs = s; bi = i; bp = k; }
        }
        #pragma unroll
        for (int o = 16; o > 0; o >>= 1) {
            float os = __shfl_down_sync(0xffffffffu, bs, o);
            int   oi = __shfl_down_sync(0xffffffffu, bi, o);
            int   op = __shfl_down_sync(0xffffffffu, bp, o);
            if (os > bs || (os == bs && oi < bi)) { bs = os; bi = oi; bp = op; }
        }
        if (lane == 0) { S.wbs[wid] = bs; S.wbi[wid] = bi; S.wbp[wid] = bp; }
        __syncthreads();
        if (tid == 0) {
            float fs = S.wbs[0]; int fi = S.wbi[0]; int fp = S.wbp[0];
            #pragma unroll
            for (int w = 1; w < 8; w++) {
                float ws = S.wbs[w]; int wi = S.wbi[w];
                if (ws > fs || (ws == fs && wi < fi)) { fs = ws; fi = wi; fp = S.wbp[w]; }
            }
            S.bests = fs; S.bestp = fp;
            S.selList[it] = fi;
            if (fs > NEG_INF) {
                float x1 = bb[fi * 4 + 0], y1 = bb[fi * 4 + 1];
                float x2 = bb[fi * 4 + 2], y2 = bb[fi * 4 + 3];
                S.bx1 = x1; S.by1 = y1; S.bx2 = x2; S.by2 = y2;
                S.barea = __fmul_rn(fmaxf(__fsub_rn(x2, x1), 0.0f),
                                    fmaxf(__fsub_rn(y2, y1), 0.0f));
            }
        }
        __syncthreads();

        if (!(S.bests > NEG_INF)) break;
        nsel = it + 1;
        int   p     = S.bestp;
        float bx1   = S.bx1, by1 = S.by1, bx2 = S.bx2, by2 = S.by2;
        float barea = S.barea;

        for (int k = tid; k < M; k += NT) {
            float s = S.score[k];
            if (s > NEG_INF) {
                int j = S.id[k];
                float x1 = bb[j * 4 + 0], y1 = bb[j * 4 + 1];
                float x2 = bb[j * 4 + 2], y2 = bb[j * 4 + 3];
                float iw = fmaxf(__fsub_rn(fminf(x2, bx2), fmaxf(x1, bx1)), 0.0f);
                float ih = fmaxf(__fsub_rn(fminf(y2, by2), fmaxf(y1, by1)), 0.0f);
                float inter  = __fmul_rn(iw, ih);
                float area_k = __fmul_rn(fmaxf(__fsub_rn(x2, x1), 0.0f),
                                         fmaxf(__fsub_rn(y2, y1), 0.0f));
                float uni = __fsub_rn(__fadd_rn(area_k, barea), inter);
                if (uni > 0.0f && __fdiv_rn(inter, uni) > iou_thr) S.score[k] = NEG_INF;
            }
        }
        if (tid == 0) S.score[p] = NEG_INF;   // iota == i (self-suppress)
        __syncthreads();
    }

    // ---- write this class's output slice as FLOAT32 triplets ----
    int rowbase3 = (b * NCLS + c) * MAXOUT * 3;
    float fb = (float)b, fc = (float)c;
    for (int k = tid; k < MAXOUT; k += NT) {
        float v0 = -1.0f, v1 = -1.0f, v2 = -1.0f;
        if (k < nsel) { v0 = fb; v1 = fc; v2 = (float)S.selList[k]; }
        out[rowbase3 + k * 3 + 0] = v0;
        out[rowbase3 + k * 3 + 1] = v1;
        out[rowbase3 + k * 3 + 2] = v2;
    }
}

extern "C" void kernel_launch(void* const* d_in, const int* in_sizes, int n_in,
                              void* d_out, int out_size)
{
    // Confirmed by R14 diagnostics: positional, element-counted.
    //   d_in[0]=boxes (262144), d_in[1]=scores (5242880),
    //   d_in[2]=max_output_boxes_per_class, d_in[3]=iou_thr, d_in[4]=score_thr
    const float* boxes  = (const float*)d_in[0];
    const float* scores = (const float*)d_in[1];
    const void*  iou_p   = (n_in > 3) ? d_in[3] : nullptr;
    const void*  score_p = (n_in > 4) ? d_in[4] : nullptr;
    (void)in_sizes; (void)out_size;

    nms_literal<<<BATCH * NCLS, NT>>>(boxes, scores, iou_p, score_p,
                                      (float*)d_out);
}

// round 16
// speedup vs baseline: 8.2030x; 8.2030x over previous
#include <cuda_runtime.h>
#include <cstdint>

// ONNX NonMaxSuppression: B=8, C=80, N=8192, max_out=100. Output = FLOAT32
// triplets (confirmed R15 pass). One CTA per (batch, class):
//   1) 256-bucket histogram on score (score > thr)
//   2) descending-bucket counting-sort scatter (score, idx)
//   3) within-bucket rank sort -> exact (score desc, idx asc) order
//   4) prefetch boxes of top-384 ranked candidates to smem
//   5) single-warp greedy walk: accept iff IoU <= thr vs all accepted
//      (accepted boxes in warp registers, 4 slots/lane; IoU in RN to match ref)
// Equivalent to the reference's iterative argmax+suppress: suppression never
// changes surviving scores, so selection order == static (score desc, idx asc)
// order filtered by the accept test; jnp.argmax tie-break == idx asc.

#define BATCH   8
#define NCLS    80
#define NBOX    8192
#define NBUCK   256
#define CAP     4608
#define TOPB    384
#define NT      256
#define MAXSEL  128
#define MAXOUT  100

struct SmemLayout {
    float          score[CAP];    // 18432
    float4         box[TOPB];     //  6144
    unsigned short idx[CAP];      //  9216
    unsigned short order[CAP];    //  9216
    int            hist[NBUCK];   //  1024
    int            offs[NBUCK];   //  1024
    int            cursor[NBUCK]; //  1024
    int            scanb[NBUCK];  //  1024
    int            selList[MAXSEL]; // 512 => 47616 B static (<48K)
};

__device__ __forceinline__ int bucket_of(float s, float thr, float invw) {
    int bk = (int)((s - thr) * invw);
    return bk < (NBUCK - 1) ? (bk < 0 ? 0 : bk) : (NBUCK - 1);
}

// Scalar may be f32 or f64; accept if in [1e-6, 1].
__device__ __forceinline__ float decode_thr(const void* p, float dflt) {
    if (p == nullptr) return dflt;
    const unsigned* u = (const unsigned*)p;
    float f32 = __uint_as_float(u[0]);
    if (f32 >= 1e-6f && f32 <= 1.0f) return f32;
    unsigned long long w = ((unsigned long long)u[1] << 32) | u[0];
    double f64 = __longlong_as_double((long long)w);
    if (f64 >= 1e-6 && f64 <= 1.0) return (float)f64;
    return dflt;
}

__global__ __launch_bounds__(NT)
void nms_sorted(const float* __restrict__ boxes,
                const float* __restrict__ scores,
                const void* iou_p, const void* score_p,
                float* __restrict__ out)
{
    __shared__ SmemLayout S;

    const int bc  = blockIdx.x;
    const int b   = bc / NCLS;
    const int c   = bc % NCLS;
    const int tid = threadIdx.x;

    const float iou_thr   = decode_thr(iou_p,   0.5f);
    const float score_thr = decode_thr(score_p, 0.5f);
    float width = 1.0f - score_thr;
    if (width < 1e-6f) width = 1e-6f;
    const float invw = (float)NBUCK / width;

    const float* sc = scores + ((size_t)b * NCLS + c) * NBOX;
    const float4* gBox = reinterpret_cast<const float4*>(boxes) + (size_t)b * NBOX;

    // ---- phase 1: histogram ----
    S.hist[tid] = 0;
    __syncthreads();
    for (int j = tid; j < NBOX; j += NT) {
        float s = sc[j];
        if (s > score_thr) atomicAdd(&S.hist[bucket_of(s, score_thr, invw)], 1);
    }
    __syncthreads();

    // ---- phase 2: descending-bucket inclusive scan (Hillis-Steele) ----
    int v = S.hist[NBUCK - 1 - tid];
    S.scanb[tid] = v;
    __syncthreads();
    #pragma unroll
    for (int o = 1; o < NBUCK; o <<= 1) {
        int x = S.scanb[tid];
        if (tid >= o) x += S.scanb[tid - o];
        __syncthreads();
        S.scanb[tid] = x;
        __syncthreads();
    }
    int incl = S.scanb[tid];
    int M    = S.scanb[NBUCK - 1];
    int mybk = NBUCK - 1 - tid;
    S.offs[mybk]   = incl - v;
    S.cursor[mybk] = incl - v;
    __syncthreads();

    int Mc = M < CAP ? M : CAP;

    // ---- phase 3: counting-sort scatter ----
    for (int j = tid; j < NBOX; j += NT) {
        float s = sc[j];
        if (s > score_thr) {
            int bk  = bucket_of(s, score_thr, invw);
            int pos = atomicAdd(&S.cursor[bk], 1);
            if (pos < CAP) { S.score[pos] = s; S.idx[pos] = (unsigned short)j; }
        }
    }
    __syncthreads();

    // ---- phase 4: within-bucket rank sort -> exact order ----
    for (int pos = tid; pos < Mc; pos += NT) {
        float s = S.score[pos];
        int   j = S.idx[pos];
        int  bk = bucket_of(s, score_thr, invw);
        int base = S.offs[bk];
        int cnt  = S.hist[bk];
        if (base + cnt > Mc) cnt = Mc - base;
        int rank = 0;
        for (int k = 0; k < cnt; k++) {
            float s2 = S.score[base + k];
            int   j2 = S.idx[base + k];
            rank += (s2 > s) || (s2 == s && j2 < j);
        }
        S.order[base + rank] = (unsigned short)pos;
    }
    __syncthreads();

    // ---- phase 4.5: prefetch boxes of top-TOPB ranked candidates ----
    {
        int lim = Mc < TOPB ? Mc : TOPB;
        for (int r = tid; r < lim; r += NT)
            S.box[r] = gBox[S.idx[S.order[r]]];
    }

    // ---- prefill this class's output slice with -1.0f ----
    int rowbase3 = (b * NCLS + c) * MAXOUT * 3;
    for (int e = tid; e < MAXOUT * 3; e += NT) out[rowbase3 + e] = -1.0f;
    __syncthreads();

    // ---- phase 5: single-warp greedy walk ----
    if (tid < 32) {
        const int lane = tid;
        float sx1[4], sy1[4], sx2[4], sy2[4], sar[4];
        int nsel = 0;

        for (int r = 0; r < Mc && nsel < MAXOUT; r++) {
            float4 bx;
            if (r < TOPB) bx = S.box[r];
            else          bx = gBox[S.idx[S.order[r]]];
            float cx1 = bx.x, cy1 = bx.y, cx2 = bx.z, cy2 = bx.w;
            float car = __fmul_rn(fmaxf(__fsub_rn(cx2, cx1), 0.0f),
                                  fmaxf(__fsub_rn(cy2, cy1), 0.0f));

            bool sup = false;
            #pragma unroll
            for (int sl = 0; sl < 4; sl++) {
                int k = sl * 32 + lane;
                if (k < nsel) {
                    float iw = fmaxf(__fsub_rn(fminf(sx2[sl], cx2), fmaxf(sx1[sl], cx1)), 0.0f);
                    float ih = fmaxf(__fsub_rn(fminf(sy2[sl], cy2), fmaxf(sy1[sl], cy1)), 0.0f);
                    float inter = __fmul_rn(iw, ih);
                    // ref: union = area(candidate-under-test) + area(selected) - inter
                    float uni = __fsub_rn(__fadd_rn(car, sar[sl]), inter);
                    if (uni > 0.0f && __fdiv_rn(inter, uni) > iou_thr) sup = true;
                }
            }
            if (!__any_sync(0xffffffffu, sup)) {
                int sl = nsel >> 5, which = nsel & 31;
                if (lane == which) {
                    sx1[sl] = cx1; sy1[sl] = cy1; sx2[sl] = cx2; sy2[sl] = cy2; sar[sl] = car;
                }
                if (lane == 0) S.selList[nsel] = S.idx[S.order[r]];
                nsel++;
            }
        }
        __syncwarp();

        float fb = (float)b, fc = (float)c;
        for (int k = lane; k < nsel; k += 32) {
            int o = rowbase3 + k * 3;
            out[o + 0] = fb;
            out[o + 1] = fc;
            out[o + 2] = (float)S.selList[k];
        }
    }
}

extern "C" void kernel_launch(void* const* d_in, const int* in_sizes, int n_in,
                              void* d_out, int out_size)
{
    // Confirmed (R14): positional inputs, element-counted sizes.
    //   d_in[0]=boxes, d_in[1]=scores, d_in[2]=max_out, d_in[3]=iou, d_in[4]=score
    const float* boxes  = (const float*)d_in[0];
    const float* scores = (const float*)d_in[1];
    const void*  iou_p   = (n_in > 3) ? d_in[3] : nullptr;
    const void*  score_p = (n_in > 4) ? d_in[4] : nullptr;
    (void)in_sizes; (void)out_size;

    nms_sorted<<<BATCH * NCLS, NT>>>(boxes, scores, iou_p, score_p,
                                     (float*)d_out);
}

// round 17
// speedup vs baseline: 12.3095x; 1.5006x over previous
#include <cuda_runtime.h>
#include <cstdint>

// ONNX NonMaxSuppression: B=8, C=80, N=8192, max_out=100. Output = f32 triplets.
// One CTA per (batch, class). R17 changes vs R16 (157.8us):
//  - smem 47.6K -> 42.5K  => 5 CTAs/SM => single wave (640 <= 740)
//  - walk software-pipelined (prefetch next box while evaluating current)
//  - slot loop early-breaks at nsel (1 div-chain when nsel<32, not 4)
//  - -1 prefill done by warps 1..7 concurrently with the warp-0 walk

#define BATCH   8
#define NCLS    80
#define NBOX    8192
#define NBUCK   256
#define CAP     4352
#define TOPB    256
#define NT      256
#define MAXSEL  128
#define MAXOUT  100

struct SmemLayout {
    float          score[CAP];    // 17408
    float4         box[TOPB];     //  4096
    unsigned short idx[CAP];      //  8704
    unsigned short order[CAP];    //  8704
    int            hist[NBUCK];   //  1024
    int            offs[NBUCK];   //  1024
    int            cursor[NBUCK]; //  1024
    int            scanb[NBUCK];  //  1024
    int            selList[MAXSEL]; // 512 => 43520 B
};

__device__ __forceinline__ int bucket_of(float s, float thr, float invw) {
    int bk = (int)((s - thr) * invw);
    return bk < (NBUCK - 1) ? (bk < 0 ? 0 : bk) : (NBUCK - 1);
}

__device__ __forceinline__ float decode_thr(const void* p, float dflt) {
    if (p == nullptr) return dflt;
    const unsigned* u = (const unsigned*)p;
    float f32 = __uint_as_float(u[0]);
    if (f32 >= 1e-6f && f32 <= 1.0f) return f32;
    unsigned long long w = ((unsigned long long)u[1] << 32) | u[0];
    double f64 = __longlong_as_double((long long)w);
    if (f64 >= 1e-6 && f64 <= 1.0) return (float)f64;
    return dflt;
}

__global__ __launch_bounds__(NT)
void nms_sorted(const float* __restrict__ boxes,
                const float* __restrict__ scores,
                const void* iou_p, const void* score_p,
                float* __restrict__ out)
{
    __shared__ SmemLayout S;

    const int bc  = blockIdx.x;
    const int b   = bc / NCLS;
    const int c   = bc % NCLS;
    const int tid = threadIdx.x;

    const float iou_thr   = decode_thr(iou_p,   0.5f);
    const float score_thr = decode_thr(score_p, 0.5f);
    float width = 1.0f - score_thr;
    if (width < 1e-6f) width = 1e-6f;
    const float invw = (float)NBUCK / width;

    const float* sc = scores + ((size_t)b * NCLS + c) * NBOX;
    const float4* gBox = reinterpret_cast<const float4*>(boxes) + (size_t)b * NBOX;

    // ---- phase 1: histogram ----
    S.hist[tid] = 0;
    __syncthreads();
    for (int j = tid; j < NBOX; j += NT) {
        float s = sc[j];
        if (s > score_thr) atomicAdd(&S.hist[bucket_of(s, score_thr, invw)], 1);
    }
    __syncthreads();

    // ---- phase 2: descending-bucket inclusive scan ----
    int v = S.hist[NBUCK - 1 - tid];
    S.scanb[tid] = v;
    __syncthreads();
    #pragma unroll
    for (int o = 1; o < NBUCK; o <<= 1) {
        int x = S.scanb[tid];
        if (tid >= o) x += S.scanb[tid - o];
        __syncthreads();
        S.scanb[tid] = x;
        __syncthreads();
    }
    int incl = S.scanb[tid];
    int M    = S.scanb[NBUCK - 1];
    int mybk = NBUCK - 1 - tid;
    S.offs[mybk]   = incl - v;
    S.cursor[mybk] = incl - v;
    __syncthreads();

    int Mc = M < CAP ? M : CAP;

    // ---- phase 3: counting-sort scatter ----
    for (int j = tid; j < NBOX; j += NT) {
        float s = sc[j];
        if (s > score_thr) {
            int bk  = bucket_of(s, score_thr, invw);
            int pos = atomicAdd(&S.cursor[bk], 1);
            if (pos < CAP) { S.score[pos] = s; S.idx[pos] = (unsigned short)j; }
        }
    }
    __syncthreads();

    // ---- phase 4: within-bucket rank sort -> exact (score desc, idx asc) ----
    for (int pos = tid; pos < Mc; pos += NT) {
        float s = S.score[pos];
        int   j = S.idx[pos];
        int  bk = bucket_of(s, score_thr, invw);
        int base = S.offs[bk];
        int cnt  = S.hist[bk];
        if (base + cnt > Mc) cnt = Mc - base;
        int rank = 0;
        for (int k = 0; k < cnt; k++) {
            float s2 = S.score[base + k];
            int   j2 = S.idx[base + k];
            rank += (s2 > s) || (s2 == s && j2 < j);
        }
        S.order[base + rank] = (unsigned short)pos;
    }
    __syncthreads();

    // ---- phase 4.5: prefetch boxes of top-TOPB ranked candidates ----
    {
        int lim = Mc < TOPB ? Mc : TOPB;
        for (int r = tid; r < lim; r += NT)
            S.box[r] = gBox[S.idx[S.order[r]]];
    }
    __syncthreads();

    int rowbase3 = (b * NCLS + c) * MAXOUT * 3;

    if (tid >= 32) {
        // ---- warps 1..7: prefill the output slice with -1.0f (concurrent
        // with the warp-0 walk; ordering vs the final triplet write is
        // enforced by the __syncthreads below) ----
        for (int e = tid - 32; e < MAXOUT * 3; e += NT - 32)
            out[rowbase3 + e] = -1.0f;
    } else {
        // ---- warp 0: greedy walk, software-pipelined ----
        const int lane = tid;
        float sx1[4], sy1[4], sx2[4], sy2[4], sar[4];
        int nsel = 0;

        float4 nb = make_float4(0.f, 0.f, 0.f, 0.f);
        if (Mc > 0) nb = (0 < TOPB) ? S.box[0] : gBox[S.idx[S.order[0]]];

        for (int r = 0; r < Mc && nsel < MAXOUT; r++) {
            float4 bx = nb;
            int rn = r + 1;
            if (rn < Mc)
                nb = (rn < TOPB) ? S.box[rn] : gBox[S.idx[S.order[rn]]];

            float cx1 = bx.x, cy1 = bx.y, cx2 = bx.z, cy2 = bx.w;
            float car = __fmul_rn(fmaxf(__fsub_rn(cx2, cx1), 0.0f),
                                  fmaxf(__fsub_rn(cy2, cy1), 0.0f));

            bool sup = false;
            #pragma unroll
            for (int sl = 0; sl < 4; sl++) {
                if ((sl << 5) >= nsel) break;   // uniform across warp
                int k = (sl << 5) + lane;
                if (k < nsel) {
                    float iw = fmaxf(__fsub_rn(fminf(sx2[sl], cx2), fmaxf(sx1[sl], cx1)), 0.0f);
                    float ih = fmaxf(__fsub_rn(fminf(sy2[sl], cy2), fmaxf(sy1[sl], cy1)), 0.0f);
                    float inter = __fmul_rn(iw, ih);
                    float uni   = __fsub_rn(__fadd_rn(car, sar[sl]), inter);
                    if (uni > 0.0f && __fdiv_rn(inter, uni) > iou_thr) sup = true;
                }
            }
            if (!__any_sync(0xffffffffu, sup)) {
                int sl = nsel >> 5, which = nsel & 31;
                if (lane == which) {
                    sx1[sl] = cx1; sy1[sl] = cy1; sx2[sl] = cx2; sy2[sl] = cy2; sar[sl] = car;
                }
                if (lane == 0) S.selList[nsel] = S.idx[S.order[r]];
                nsel++;
            }
        }
        __syncwarp();
        if (lane == 0) S.cursor[0] = nsel;   // publish nsel (cursor is dead now)
    }
    __syncthreads();

    // ---- warp 0 writes the selected triplets over the prefilled slice ----
    if (tid < 32) {
        int nsel = S.cursor[0];
        float fb = (float)b, fc = (float)c;
        for (int k = tid; k < nsel; k += 32) {
            int o = rowbase3 + k * 3;
            out[o + 0] = fb;
            out[o + 1] = fc;
            out[o + 2] = (float)S.selList[k];
        }
    }
}

extern "C" void kernel_launch(void* const* d_in, const int* in_sizes, int n_in,
                              void* d_out, int out_size)
{
    // Confirmed (R14): positional inputs, element-counted sizes.
    //   d_in[0]=boxes, d_in[1]=scores, d_in[2]=max_out, d_in[3]=iou, d_in[4]=score
    const float* boxes  = (const float*)d_in[0];
    const float* scores = (const float*)d_in[1];
    const void*  iou_p   = (n_in > 3) ? d_in[3] : nullptr;
    const void*  score_p = (n_in > 4) ? d_in[4] : nullptr;
    (void)in_sizes; (void)out_size;

    nms_sorted<<<BATCH * NCLS, NT>>>(boxes, scores, iou_p, score_p,
                                     (float*)d_out);
}